// round 11
// baseline (speedup 1.0000x reference)
#include <cuda_runtime.h>
#include <cuda_bf16.h>

// PearsonLoss: x1 [8,32,256,256] f32, x2 same, margin [8,256,256] i32 -> scalar f32
//
// Streaming formulation over C=32 channels (no probability storage):
//   e1=exp(x1), e2=exp(x2); S1,S2,S11,S22,S12 running sums.
//   EX=EY=1/C exactly (softmax sums to 1).
//   score = (S12/(S1*S2*C) - 1/C^2) / sqrt((S11/(S1^2 C)-1/C^2)(S22/(S2^2 C)-1/C^2))
//   per_pixel = margin==0 ? 1-score : max(score,0);  out = mean.
//
// R11 = R10 resubmitted verbatim (R10 bench was a broker/container infra
// failure; this source has never been measured).
// R10: WAVE-BALANCE fix. All direct-LDG variants measured 28.1-28.7us bench
// because work/capacity = 3.46 block-slots per 3 resident (2^19 px vs 148 SMs
// containing prime 37): a ~15% remainder always runs as a degraded tail.
//  - One exact wave: grid = 444 = 3 blocks/SM x 148.
//  - Work = 16384 groups of 32px (1 px/lane, LDG.32 = same 128B line per
//    warp per channel as before). Balanced range partition per warp:
//    [w*512/111, (w+1)*512/111) -> 4 or 5 groups each, heavy warps
//    interleaved every ~2.2 warps so every SM's 24 warps carry equal load
//    (+-0.4%). 3552*512/111 = 16384 exactly. No atomics, no per-group sync.

#define C_CH   32
#define HW     65536          // 256*256
#define NPIX   524288
#define BLOCK_SIZE 256
#define NBLOCKS 444           // 3 blocks/SM * 148 SMs: one exact wave
#define NWARPS  (NBLOCKS * BLOCK_SIZE / 32)   // 3552
#define NGROUPS (NPIX / 32)                   // 16384 = NWARPS*512/111

__device__ float        g_acc   = 0.0f;
__device__ unsigned int g_count = 0u;

__device__ __forceinline__ float finalize_pixel(float s1, float s2,
                                                float s11, float s22, float s12,
                                                int m) {
    const float invC  = 1.0f / 32.0f;
    const float invC2 = invC * invC;
    float r1 = __frcp_rn(s1);
    float r2 = __frcp_rn(s2);
    float vx  = fmaf(s11 * r1 * r1, invC, -invC2);   // EX2 - EX^2
    float vy  = fmaf(s22 * r2 * r2, invC, -invC2);   // EY2 - EY^2
    float num = fmaf(s12 * r1 * r2, invC, -invC2);   // EXY - EX*EY
    float score = num * rsqrtf(vx * vy);
    return (m == 0) ? (1.0f - score) : fmaxf(score, 0.0f);
}

__global__ void __launch_bounds__(BLOCK_SIZE)
pearson_loss_kernel(const float* __restrict__ x1,
                    const float* __restrict__ x2,
                    const int*   __restrict__ margin,
                    float* __restrict__ out) {
    const int lane = threadIdx.x & 31;
    const int w    = (blockIdx.x * BLOCK_SIZE + threadIdx.x) >> 5;  // 0..3551

    // Balanced range partition: groups [w*512/111, (w+1)*512/111).
    const int glo = (w * 512) / 111;
    const int ghi = ((w + 1) * 512) / 111;

    float local = 0.0f;

    for (int g = glo; g < ghi; g++) {
        const int px = g * 32 + lane;          // warp covers 32 contiguous px
        const int b  = px >> 16;               // / HW
        const int hw = px & (HW - 1);

        const float* __restrict__ p1 = x1 + ((size_t)(b * C_CH) << 16) + hw;
        const float* __restrict__ p2 = x2 + ((size_t)(b * C_CH) << 16) + hw;

        float S1 = 0.f, S2 = 0.f, S11 = 0.f, S22 = 0.f, S12 = 0.f;
#pragma unroll 8
        for (int c = 0; c < C_CH; c++) {
            float a = __ldg(p1 + ((size_t)c << 16));
            float v = __ldg(p2 + ((size_t)c << 16));
            float e1 = __expf(a);
            float e2 = __expf(v);
            S1 += e1; S2 += e2;
            S11 = fmaf(e1, e1, S11);
            S22 = fmaf(e2, e2, S22);
            S12 = fmaf(e1, e2, S12);
        }
        const int m = __ldg(&margin[px]);
        local += finalize_pixel(S1, S2, S11, S22, S12, m);
    }

    // warp reduce
#pragma unroll
    for (int off = 16; off > 0; off >>= 1)
        local += __shfl_xor_sync(0xFFFFFFFF, local, off);

    __shared__ float warp_sums[BLOCK_SIZE / 32];
    const int wid = threadIdx.x >> 5;
    if (lane == 0) warp_sums[wid] = local;
    __syncthreads();

    __shared__ bool is_last;
    if (threadIdx.x == 0) {
        float s = warp_sums[0];
#pragma unroll
        for (int q = 1; q < BLOCK_SIZE / 32; q++) s += warp_sums[q];
        atomicAdd(&g_acc, s);
        __threadfence();
        unsigned prev = atomicAdd(&g_count, 1u);
        is_last = (prev == (unsigned)(NBLOCKS - 1));
    }
    __syncthreads();

    if (is_last && threadIdx.x == 0) {
        __threadfence();  // make all g_acc contributions visible
        float total = *((volatile float*)&g_acc);
        out[0] = total * (1.0f / (float)NPIX);
        // reset for next graph replay (deterministic relaunch)
        g_acc   = 0.0f;
        g_count = 0u;
    }
}

extern "C" void kernel_launch(void* const* d_in, const int* in_sizes, int n_in,
                              void* d_out, int out_size) {
    const float* x1     = (const float*)d_in[0];
    const float* x2     = (const float*)d_in[1];
    const int*   margin = (const int*)d_in[2];
    float* out = (float*)d_out;

    pearson_loss_kernel<<<NBLOCKS, BLOCK_SIZE>>>(x1, x2, margin, out);
}

// round 12
// speedup vs baseline: 2.0737x; 2.0737x over previous
#include <cuda_runtime.h>
#include <cuda_bf16.h>

// PearsonLoss: x1 [8,32,256,256] f32, x2 same, margin [8,256,256] i32 -> scalar f32
//
// Streaming formulation over C=32 channels (no probability storage):
//   e1=exp(x1), e2=exp(x2); S1,S2,S11,S22,S12 running sums.
//   EX=EY=1/C exactly (softmax sums to 1).
//   score = (S12/(S1*S2*C) - 1/C^2) / sqrt((S11/(S1^2 C)-1/C^2)(S22/(S2^2 C)-1/C^2))
//   per_pixel = margin==0 ? 1-score : max(score,0);  out = mean.
//
// R12: CHANNEL-SWEEP DESYNC. R11 post-mortem: the LDG.32 wave-balance test
// regressed 2x (narrow loads killed per-warp wavefront MLP), not a valid test
// of balance. Remaining untested mechanism for the 63%-DRAM plateau: all
// warps sweep channels in lockstep (everyone at c~same time), so instantaneous
// traffic concentrates on a ~4-8MB slice of the 134MB footprint at 2^18-byte
// aligned strides (LTS-hash/DRAM-bank concentration). Fix: per-block rotation
// of the channel visiting order, (blockIdx*5)&31. Sums are order-invariant.
// Hot loop otherwise IDENTICAL to the measured-best R1 shape:
// BLOCK=256, 4px/thread, float4 __ldg, grid 512. Single-launch finalize.

#define C_CH   32
#define HW     65536          // 256*256
#define NBATCH 8
#define NPIX   (NBATCH * HW)  // 524288
#define PIX_PER_THREAD 4
#define NTHREADS_TOTAL (NPIX / PIX_PER_THREAD)  // 131072
#define BLOCK_SIZE 256
#define NBLOCKS (NTHREADS_TOTAL / BLOCK_SIZE)   // 512

__device__ float        g_acc   = 0.0f;
__device__ unsigned int g_count = 0u;

__device__ __forceinline__ float finalize_pixel(float s1, float s2,
                                                float s11, float s22, float s12,
                                                int m) {
    const float invC  = 1.0f / 32.0f;
    const float invC2 = invC * invC;
    float r1 = __frcp_rn(s1);
    float r2 = __frcp_rn(s2);
    float vx  = fmaf(s11 * r1 * r1, invC, -invC2);   // EX2 - EX^2
    float vy  = fmaf(s22 * r2 * r2, invC, -invC2);   // EY2 - EY^2
    float num = fmaf(s12 * r1 * r2, invC, -invC2);   // EXY - EX*EY
    float score = num * rsqrtf(vx * vy);
    return (m == 0) ? (1.0f - score) : fmaxf(score, 0.0f);
}

__global__ void __launch_bounds__(BLOCK_SIZE)
pearson_loss_kernel(const float* __restrict__ x1,
                    const float* __restrict__ x2,
                    const int*   __restrict__ margin,
                    float* __restrict__ out) {
    const int t  = blockIdx.x * BLOCK_SIZE + threadIdx.x;  // 0..131071
    const int p0 = t * PIX_PER_THREAD;                     // base pixel
    const int b  = p0 >> 16;                               // / HW
    const int hw = p0 & (HW - 1);

    const float4* __restrict__ x1p =
        (const float4*)(x1 + (size_t)b * C_CH * HW + hw);
    const float4* __restrict__ x2p =
        (const float4*)(x2 + (size_t)b * C_CH * HW + hw);
    const int cstride4 = HW / 4;   // float4 stride per channel

    // Per-block channel rotation: desynchronize the global channel sweep so
    // concurrent blocks read from different 256KB channel regions.
    const int rot = (blockIdx.x * 5) & (C_CH - 1);

    float4 S1  = make_float4(0.f, 0.f, 0.f, 0.f);
    float4 S2  = make_float4(0.f, 0.f, 0.f, 0.f);
    float4 S11 = make_float4(0.f, 0.f, 0.f, 0.f);
    float4 S22 = make_float4(0.f, 0.f, 0.f, 0.f);
    float4 S12 = make_float4(0.f, 0.f, 0.f, 0.f);

#pragma unroll 8
    for (int g = 0; g < C_CH; g++) {
        const int c = (g + rot) & (C_CH - 1);
        float4 a = __ldg(&x1p[c * cstride4]);
        float4 v = __ldg(&x2p[c * cstride4]);

        float e1, e2;
        e1 = __expf(a.x); e2 = __expf(v.x);
        S1.x += e1; S2.x += e2;
        S11.x = fmaf(e1, e1, S11.x); S22.x = fmaf(e2, e2, S22.x);
        S12.x = fmaf(e1, e2, S12.x);

        e1 = __expf(a.y); e2 = __expf(v.y);
        S1.y += e1; S2.y += e2;
        S11.y = fmaf(e1, e1, S11.y); S22.y = fmaf(e2, e2, S22.y);
        S12.y = fmaf(e1, e2, S12.y);

        e1 = __expf(a.z); e2 = __expf(v.z);
        S1.z += e1; S2.z += e2;
        S11.z = fmaf(e1, e1, S11.z); S22.z = fmaf(e2, e2, S22.z);
        S12.z = fmaf(e1, e2, S12.z);

        e1 = __expf(a.w); e2 = __expf(v.w);
        S1.w += e1; S2.w += e2;
        S11.w = fmaf(e1, e1, S11.w); S22.w = fmaf(e2, e2, S22.w);
        S12.w = fmaf(e1, e2, S12.w);
    }

    const int4 mg = __ldg(&((const int4*)margin)[t]);

    float local = finalize_pixel(S1.x, S2.x, S11.x, S22.x, S12.x, mg.x)
                + finalize_pixel(S1.y, S2.y, S11.y, S22.y, S12.y, mg.y)
                + finalize_pixel(S1.z, S2.z, S11.z, S22.z, S12.z, mg.z)
                + finalize_pixel(S1.w, S2.w, S11.w, S22.w, S12.w, mg.w);

    // warp reduce
#pragma unroll
    for (int off = 16; off > 0; off >>= 1)
        local += __shfl_xor_sync(0xFFFFFFFF, local, off);

    __shared__ float warp_sums[BLOCK_SIZE / 32];
    const int lane = threadIdx.x & 31;
    const int wid  = threadIdx.x >> 5;
    if (lane == 0) warp_sums[wid] = local;
    __syncthreads();

    __shared__ bool is_last;
    if (threadIdx.x == 0) {
        float s = warp_sums[0];
#pragma unroll
        for (int w = 1; w < BLOCK_SIZE / 32; w++) s += warp_sums[w];
        atomicAdd(&g_acc, s);
        __threadfence();
        unsigned prev = atomicAdd(&g_count, 1u);
        is_last = (prev == (unsigned)(NBLOCKS - 1));
    }
    __syncthreads();

    if (is_last && threadIdx.x == 0) {
        __threadfence();  // make all g_acc contributions visible
        float total = *((volatile float*)&g_acc);
        out[0] = total * (1.0f / (float)NPIX);
        // reset for next graph replay (deterministic relaunch)
        g_acc   = 0.0f;
        g_count = 0u;
    }
}

extern "C" void kernel_launch(void* const* d_in, const int* in_sizes, int n_in,
                              void* d_out, int out_size) {
    const float* x1     = (const float*)d_in[0];
    const float* x2     = (const float*)d_in[1];
    const int*   margin = (const int*)d_in[2];
    float* out = (float*)d_out;

    pearson_loss_kernel<<<NBLOCKS, BLOCK_SIZE>>>(x1, x2, margin, out);
}

// round 13
// speedup vs baseline: 2.0923x; 1.0090x over previous
#include <cuda_runtime.h>
#include <cuda_bf16.h>

// PearsonLoss: x1 [8,32,256,256] f32, x2 same, margin [8,256,256] i32 -> scalar f32
//
// Streaming formulation over C=32 channels (no probability storage):
//   e1=exp(x1), e2=exp(x2); S1,S2,S11,S22,S12 running sums.
//   EX=EY=1/C exactly (softmax sums to 1).
//   score = (S12/(S1*S2*C) - 1/C^2) / sqrt((S11/(S1^2 C)-1/C^2)(S22/(S2^2 C)-1/C^2))
//   per_pixel = margin==0 ? 1-score : max(score,0);  out = mean.
//
// R13: LOAD-FLAVOR experiment (single variable vs R5, the best-measured
// kernel at 28.13us bench). All SIMT-side mechanisms are exhausted: occupancy
// up/down, MLP batching, block shape, load width, channel desync all left the
// plateau at ~5.1TB/s. Little's law (19 B/cyc/SM x ~600cyc ~= 90 outstanding
// sectors/SM) points at an L1-allocation/MSHR-scale outstanding-request cap.
// B300 microarch notes the ~6300 B/cyc chip path cap was measured with
// LDG.cv (non-allocating). Data is single-touch: L1 allocation buys nothing.
//  -> __ldcs replaced with __ldcv on x1/x2 streams. NOTHING else changed.

#define C_CH   32
#define HW     65536          // 256*256
#define NBATCH 8
#define NPIX   (NBATCH * HW)  // 524288
#define PIX_PER_THREAD 4
#define NTHREADS_TOTAL (NPIX / PIX_PER_THREAD)  // 131072
#define BLOCK_SIZE 128
#define NBLOCKS (NTHREADS_TOTAL / BLOCK_SIZE)   // 1024
#define CH_GROUP 4
#define N_GROUPS (C_CH / CH_GROUP)              // 8

__device__ float        g_acc   = 0.0f;
__device__ unsigned int g_count = 0u;

__device__ __forceinline__ float finalize_pixel(float s1, float s2,
                                                float s11, float s22, float s12,
                                                int m) {
    const float invC  = 1.0f / 32.0f;
    const float invC2 = invC * invC;
    float r1 = __frcp_rn(s1);
    float r2 = __frcp_rn(s2);
    float vx  = fmaf(s11 * r1 * r1, invC, -invC2);   // EX2 - EX^2
    float vy  = fmaf(s22 * r2 * r2, invC, -invC2);   // EY2 - EY^2
    float num = fmaf(s12 * r1 * r2, invC, -invC2);   // EXY - EX*EY
    float score = num * rsqrtf(vx * vy);
    return (m == 0) ? (1.0f - score) : fmaxf(score, 0.0f);
}

__global__ void __launch_bounds__(BLOCK_SIZE, 7)
pearson_loss_kernel(const float* __restrict__ x1,
                    const float* __restrict__ x2,
                    const int*   __restrict__ margin,
                    float* __restrict__ out) {
    const int t  = blockIdx.x * BLOCK_SIZE + threadIdx.x;  // 0..131071
    const int p0 = t * PIX_PER_THREAD;                     // base pixel
    const int b  = p0 >> 16;                               // / HW
    const int hw = p0 & (HW - 1);

    const float4* __restrict__ x1p =
        (const float4*)(x1 + (size_t)b * C_CH * HW + hw);
    const float4* __restrict__ x2p =
        (const float4*)(x2 + (size_t)b * C_CH * HW + hw);
    const int cstride4 = HW / 4;   // float4 stride per channel

    float4 S1  = make_float4(0.f, 0.f, 0.f, 0.f);
    float4 S2  = make_float4(0.f, 0.f, 0.f, 0.f);
    float4 S11 = make_float4(0.f, 0.f, 0.f, 0.f);
    float4 S22 = make_float4(0.f, 0.f, 0.f, 0.f);
    float4 S12 = make_float4(0.f, 0.f, 0.f, 0.f);

#pragma unroll
    for (int g = 0; g < N_GROUPS; g++) {
        // Batch-issue all 8 loads of this group before any compute.
        float4 a[CH_GROUP], v[CH_GROUP];
#pragma unroll
        for (int j = 0; j < CH_GROUP; j++) {
            const int c = g * CH_GROUP + j;
            a[j] = __ldcv(&x1p[c * cstride4]);   // .cv: non-allocating load
            v[j] = __ldcv(&x2p[c * cstride4]);
        }
#pragma unroll
        for (int j = 0; j < CH_GROUP; j++) {
            float e1, e2;
            e1 = __expf(a[j].x); e2 = __expf(v[j].x);
            S1.x += e1; S2.x += e2;
            S11.x = fmaf(e1, e1, S11.x); S22.x = fmaf(e2, e2, S22.x);
            S12.x = fmaf(e1, e2, S12.x);

            e1 = __expf(a[j].y); e2 = __expf(v[j].y);
            S1.y += e1; S2.y += e2;
            S11.y = fmaf(e1, e1, S11.y); S22.y = fmaf(e2, e2, S22.y);
            S12.y = fmaf(e1, e2, S12.y);

            e1 = __expf(a[j].z); e2 = __expf(v[j].z);
            S1.z += e1; S2.z += e2;
            S11.z = fmaf(e1, e1, S11.z); S22.z = fmaf(e2, e2, S22.z);
            S12.z = fmaf(e1, e2, S12.z);

            e1 = __expf(a[j].w); e2 = __expf(v[j].w);
            S1.w += e1; S2.w += e2;
            S11.w = fmaf(e1, e1, S11.w); S22.w = fmaf(e2, e2, S22.w);
            S12.w = fmaf(e1, e2, S12.w);
        }
    }

    const int4 mg = __ldg(&((const int4*)margin)[t]);

    float local = finalize_pixel(S1.x, S2.x, S11.x, S22.x, S12.x, mg.x)
                + finalize_pixel(S1.y, S2.y, S11.y, S22.y, S12.y, mg.y)
                + finalize_pixel(S1.z, S2.z, S11.z, S22.z, S12.z, mg.z)
                + finalize_pixel(S1.w, S2.w, S11.w, S22.w, S12.w, mg.w);

    // warp reduce
#pragma unroll
    for (int off = 16; off > 0; off >>= 1)
        local += __shfl_xor_sync(0xFFFFFFFF, local, off);

    __shared__ float warp_sums[BLOCK_SIZE / 32];
    const int lane = threadIdx.x & 31;
    const int wid  = threadIdx.x >> 5;
    if (lane == 0) warp_sums[wid] = local;
    __syncthreads();

    __shared__ bool is_last;
    if (threadIdx.x == 0) {
        float s = warp_sums[0];
#pragma unroll
        for (int w = 1; w < BLOCK_SIZE / 32; w++) s += warp_sums[w];
        atomicAdd(&g_acc, s);
        __threadfence();
        unsigned prev = atomicAdd(&g_count, 1u);
        is_last = (prev == (unsigned)(NBLOCKS - 1));
    }
    __syncthreads();

    if (is_last && threadIdx.x == 0) {
        __threadfence();  // make all g_acc contributions visible
        float total = *((volatile float*)&g_acc);
        out[0] = total * (1.0f / (float)NPIX);
        // reset for next graph replay (deterministic relaunch)
        g_acc   = 0.0f;
        g_count = 0u;
    }
}

extern "C" void kernel_launch(void* const* d_in, const int* in_sizes, int n_in,
                              void* d_out, int out_size) {
    const float* x1     = (const float*)d_in[0];
    const float* x2     = (const float*)d_in[1];
    const int*   margin = (const int*)d_in[2];
    float* out = (float*)d_out;

    pearson_loss_kernel<<<NBLOCKS, BLOCK_SIZE>>>(x1, x2, margin, out);
}